// round 5
// baseline (speedup 1.0000x reference)
#include <cuda_runtime.h>
#include <cuda_bf16.h>
#include <cstddef>

// Problem constants
#define NCH 16
#define ND  64
#define NH  96
#define NW  96
#define PLANE (NH*NW)            // 9216
#define CH_STRIDE (ND*NH*NW)     // 589824
#define KOUT 8
#define NTILE 18                 // 2 z-halves * 9 hw tiles

typedef unsigned long long u64;

// ---- f32x2 packed helpers (sm_103a) ----
__device__ __forceinline__ u64 pk2(float a, float b) {
    u64 r; asm("mov.b64 %0,{%1,%2};" : "=l"(r) : "f"(a), "f"(b)); return r;
}
__device__ __forceinline__ void upk2(u64 v, float& a, float& b) {
    asm("mov.b64 {%0,%1},%2;" : "=f"(a), "=f"(b) : "l"(v));
}
__device__ __forceinline__ u64 add2(u64 a, u64 b) {
    u64 r; asm("add.rn.f32x2 %0,%1,%2;" : "=l"(r) : "l"(a), "l"(b)); return r;
}
__device__ __forceinline__ u64 mul2(u64 a, u64 b) {
    u64 r; asm("mul.rn.f32x2 %0,%1,%2;" : "=l"(r) : "l"(a), "l"(b)); return r;
}
__device__ __forceinline__ u64 fma2(u64 a, u64 b, u64 c) {
    u64 r; asm("fma.rn.f32x2 %0,%1,%2,%3;" : "=l"(r) : "l"(a), "l"(b), "l"(c)); return r;
}

__device__ float g_part[NCH * NTILE];
__device__ int   g_idx[KOUT];

__global__ __launch_bounds__(512, 2) void harris_kernel(const float* __restrict__ x) {
    __shared__ float2 AB[36 * 38];        // (A, BZ) interleaved, row stride 38
    __shared__ float  GX[34 * 36];
    __shared__ float  GY[34 * 36];
    __shared__ float  GZ[34 * 36];
    __shared__ float  RED[16];

    const int tid   = threadIdx.x;
    const int c     = blockIdx.z >> 1;
    const int zhalf = blockIdx.z & 1;
    const int h0    = blockIdx.y * 32;
    const int w0    = blockIdx.x * 32;
    const float* xc = x + (size_t)c * CH_STRIDE;

    const int z0 = zhalf * 32;
    const int z1 = z0 + 32;
    const int s_begin = (z0 == 0) ? 0 : z0 - 1;
    const int s_end   = (z1 == ND) ? ND - 1 : z1;   // inclusive

    // ---- per-thread owned pixels of the 36x36 extended grid (up to 3) ----
    int offs[3];
#pragma unroll
    for (int k = 0; k < 3; k++) {
        int idx = tid + k * 512;
        if (idx < 36*36) {
            int i = idx / 36, j = idx % 36;
            int gh = h0 + i - 2, gw = w0 + j - 2;
            offs[k] = ((unsigned)gh < (unsigned)NH && (unsigned)gw < (unsigned)NW)
                      ? gh*NW + gw : -1;
        } else offs[k] = -1;
    }

    // x-depth ring: xm = x(t-1), x0r = x(t), where next st1 writes slice t
    float xm[3], x0r[3];
#pragma unroll
    for (int k = 0; k < 3; k++) {
        xm[k] = 0.f; x0r[k] = 0.f;
        if (offs[k] >= 0) {
            if (s_begin - 1 >= 0) xm[k] = xc[(size_t)(s_begin-1)*PLANE + offs[k]];
            x0r[k] = xc[(size_t)s_begin*PLANE + offs[k]];
        }
    }

    // fused-stage ownership: 2 vertical pixels (rows r0, r0+1), col tw
    const int tw = tid & 31;
    const int r0 = (tid >> 5) * 2;

    u64 A1[6], A2[6];
    const u64 ZERO2 = pk2(0.f, 0.f);
#pragma unroll
    for (int k = 0; k < 6; k++) { A1[k] = ZERO2; A2[k] = ZERO2; }
    u64 hsum2 = ZERO2;
    const u64 C1v  = pk2(1.f/19683.f, 1.f/19683.f);   // 1/27^3
    const u64 C2v  = pk2(0.04f/729.f, 0.04f/729.f);   // k/27^2
    const u64 NEG1 = pk2(-1.f, -1.f);
    const u64 TWO2 = pk2(2.f, 2.f);

#define SUB2(a, b) fma2((b), NEG1, (a))

#define DO_ST1(T) do {                                                         \
    int t_ = (T);                                                              \
    _Pragma("unroll")                                                          \
    for (int k = 0; k < 3; k++) {                                              \
        int idx = tid + k * 512;                                               \
        if (k < 2 || idx < 36*36) {                                            \
            float xpv = 0.f;                                                   \
            if (offs[k] >= 0 && t_ + 1 < ND)                                   \
                xpv = xc[(size_t)(t_+1)*PLANE + offs[k]];                      \
            int i = idx / 36, j = idx % 36;                                    \
            AB[i*38 + j] = make_float2(xm[k] + x0r[k] + xpv, xpv - xm[k]);     \
            xm[k] = x0r[k]; x0r[k] = xpv;                                      \
        }                                                                      \
    }                                                                          \
} while (0)

// stage2: column-pair-packed gradients (2x2 outputs per thread, 289 threads)
#define DO_ST2() do {                                                          \
    if (tid < 289) {                                                           \
        int i0 = (tid / 17) * 2, j0 = (tid % 17) * 2;                          \
        u64 hd[4], h121[4], rs[4];                                             \
        _Pragma("unroll")                                                      \
        for (int r = 0; r < 4; r++) {                                          \
            const float4* p = reinterpret_cast<const float4*>(AB + ((i0+r)*38 + j0)); \
            float4 u = p[0], v = p[1];                                         \
            u64 A01 = pk2(u.x, u.z);                                           \
            u64 A12 = pk2(u.z, v.x);                                           \
            u64 A23 = pk2(v.x, v.z);                                           \
            u64 B01 = pk2(u.y, u.w);                                           \
            u64 B12 = pk2(u.w, v.y);                                           \
            u64 B23 = pk2(v.y, v.w);                                           \
            hd[r]   = SUB2(A23, A01);                                          \
            h121[r] = fma2(A12, TWO2, add2(A01, A23));                         \
            rs[r]   = add2(add2(B01, B12), B23);                               \
        }                                                                      \
        _Pragma("unroll")                                                      \
        for (int rr = 0; rr < 2; rr++) {                                       \
            int go = (i0+rr)*36 + j0;                                          \
            u64 gx = fma2(hd[rr+1], TWO2, add2(hd[rr], hd[rr+2]));             \
            u64 gy = SUB2(h121[rr+2], h121[rr]);                               \
            u64 gz = add2(add2(rs[rr], rs[rr+1]), rs[rr+2]);                   \
            float a_, b_;                                                      \
            upk2(gx, a_, b_); *reinterpret_cast<float2*>(GX + go) = make_float2(a_, b_); \
            upk2(gy, a_, b_); *reinterpret_cast<float2*>(GY + go) = make_float2(a_, b_); \
            upk2(gz, a_, b_); *reinterpret_cast<float2*>(GZ + go) = make_float2(a_, b_); \
        }                                                                      \
    }                                                                          \
} while (0)

    // ---- prologue: st1(s_begin), st2(s_begin) ----
    DO_ST1(s_begin);
    __syncthreads();
    DO_ST2();
    __syncthreads();

    // ================= main loop =================
    for (int s = s_begin; s <= s_end; s++) {
        const bool more = (s < s_end);

        // ---------- phase A: prefetch x(s+2), fused st3+4(s), st1-store(s+1) ----------
        float xpv[3];
        if (more) {
#pragma unroll
            for (int k = 0; k < 3; k++) {
                xpv[k] = 0.f;
                if (offs[k] >= 0 && s + 2 < ND)
                    xpv[k] = xc[(size_t)(s+2)*PLANE + offs[k]];
            }
        }

        // fused stage3+4 on slice s: row-pair-packed products
        {
            u64 cur[6];
            // pair 0: grad rows r0, r0+1  (c0 gets both, c1 gets row r0+1)
            {
                int b = r0*36 + tw;
                u64 X0 = pk2(GX[b],   GX[b+36]);
                u64 X1 = pk2(GX[b+1], GX[b+37]);
                u64 X2 = pk2(GX[b+2], GX[b+38]);
                u64 Y0 = pk2(GY[b],   GY[b+36]);
                u64 Y1 = pk2(GY[b+1], GY[b+37]);
                u64 Y2 = pk2(GY[b+2], GY[b+38]);
                u64 Z0 = pk2(GZ[b],   GZ[b+36]);
                u64 Z1 = pk2(GZ[b+1], GZ[b+37]);
                u64 Z2 = pk2(GZ[b+2], GZ[b+38]);
                float lo, hi; u64 q;
                q = fma2(X0,X0, fma2(X1,X1, mul2(X2,X2)));
                upk2(q, lo, hi); cur[0] = pk2(lo + hi, hi);
                q = fma2(Y0,Y0, fma2(Y1,Y1, mul2(Y2,Y2)));
                upk2(q, lo, hi); cur[1] = pk2(lo + hi, hi);
                q = fma2(Z0,Z0, fma2(Z1,Z1, mul2(Z2,Z2)));
                upk2(q, lo, hi); cur[2] = pk2(lo + hi, hi);
                q = fma2(X0,Y0, fma2(X1,Y1, mul2(X2,Y2)));
                upk2(q, lo, hi); cur[3] = pk2(lo + hi, hi);
                q = fma2(X0,Z0, fma2(X1,Z1, mul2(X2,Z2)));
                upk2(q, lo, hi); cur[4] = pk2(lo + hi, hi);
                q = fma2(Y0,Z0, fma2(Y1,Z1, mul2(Y2,Z2)));
                upk2(q, lo, hi); cur[5] = pk2(lo + hi, hi);
            }
            // pair 1: grad rows r0+2, r0+3  (c0 gets row r0+2, c1 gets both)
            {
                int b = (r0+2)*36 + tw;
                u64 X0 = pk2(GX[b],   GX[b+36]);
                u64 X1 = pk2(GX[b+1], GX[b+37]);
                u64 X2 = pk2(GX[b+2], GX[b+38]);
                u64 Y0 = pk2(GY[b],   GY[b+36]);
                u64 Y1 = pk2(GY[b+1], GY[b+37]);
                u64 Y2 = pk2(GY[b+2], GY[b+38]);
                u64 Z0 = pk2(GZ[b],   GZ[b+36]);
                u64 Z1 = pk2(GZ[b+1], GZ[b+37]);
                u64 Z2 = pk2(GZ[b+2], GZ[b+38]);
                float lo, hi; u64 q;
                q = fma2(X0,X0, fma2(X1,X1, mul2(X2,X2)));
                upk2(q, lo, hi); cur[0] = add2(cur[0], pk2(lo, lo + hi));
                q = fma2(Y0,Y0, fma2(Y1,Y1, mul2(Y2,Y2)));
                upk2(q, lo, hi); cur[1] = add2(cur[1], pk2(lo, lo + hi));
                q = fma2(Z0,Z0, fma2(Z1,Z1, mul2(Z2,Z2)));
                upk2(q, lo, hi); cur[2] = add2(cur[2], pk2(lo, lo + hi));
                q = fma2(X0,Y0, fma2(X1,Y1, mul2(X2,Y2)));
                upk2(q, lo, hi); cur[3] = add2(cur[3], pk2(lo, lo + hi));
                q = fma2(X0,Z0, fma2(X1,Z1, mul2(X2,Z2)));
                upk2(q, lo, hi); cur[4] = add2(cur[4], pk2(lo, lo + hi));
                q = fma2(Y0,Z0, fma2(Y1,Z1, mul2(Y2,Z2)));
                upk2(q, lo, hi); cur[5] = add2(cur[5], pk2(lo, lo + hi));
            }

            int d = s - 1;
            if (d >= z0) {
                u64 sxx = add2(A2[0], cur[0]);
                u64 syy = add2(A2[1], cur[1]);
                u64 szz = add2(A2[2], cur[2]);
                u64 sxy = add2(A2[3], cur[3]);
                u64 sxz = add2(A2[4], cur[4]);
                u64 syz = add2(A2[5], cur[5]);
                u64 m1  = SUB2(mul2(syy, szz), mul2(syz, syz));
                u64 m2  = SUB2(mul2(sxy, szz), mul2(syz, sxz));
                u64 m3  = SUB2(mul2(sxy, syz), mul2(syy, sxz));
                u64 det = SUB2(fma2(sxx, m1, mul2(sxz, m3)), mul2(sxy, m2));
                u64 tr  = add2(add2(sxx, syy), szz);
                u64 h   = SUB2(mul2(det, C1v), mul2(mul2(tr, tr), C2v));
                hsum2 = add2(hsum2, h);
            }
#pragma unroll
            for (int k = 0; k < 6; k++) { A2[k] = add2(A1[k], cur[k]); A1[k] = cur[k]; }
        }

        // st1 stores for slice s+1 (consumes prefetched xpv)
        if (more) {
#pragma unroll
            for (int k = 0; k < 3; k++) {
                int idx = tid + k * 512;
                if (k < 2 || idx < 36*36) {
                    int i = idx / 36, j = idx % 36;
                    AB[i*38 + j] = make_float2(xm[k] + x0r[k] + xpv[k], xpv[k] - xm[k]);
                    xm[k] = x0r[k]; x0r[k] = xpv[k];
                }
            }
        }
        __syncthreads();

        // ---------- phase B: st2(s+1): AB -> G ----------
        if (more) {
            DO_ST2();
        }
        __syncthreads();
    }

    // tail: output depth ND-1 (slice at ND contributes 0)
    if (z1 == ND) {
        u64 sxx = A2[0], syy = A2[1], szz = A2[2];
        u64 sxy = A2[3], sxz = A2[4], syz = A2[5];
        u64 m1  = SUB2(mul2(syy, szz), mul2(syz, syz));
        u64 m2  = SUB2(mul2(sxy, szz), mul2(syz, sxz));
        u64 m3  = SUB2(mul2(sxy, syz), mul2(syy, sxz));
        u64 det = SUB2(fma2(sxx, m1, mul2(sxz, m3)), mul2(sxy, m2));
        u64 tr  = add2(add2(sxx, syy), szz);
        u64 h   = SUB2(mul2(det, C1v), mul2(mul2(tr, tr), C2v));
        hsum2 = add2(hsum2, h);
    }

    // ---- reduction -> g_part (non-atomic, deterministic) ----
    float ha, hb;
    upk2(hsum2, ha, hb);
    float hsum = ha + hb;
#pragma unroll
    for (int o = 16; o > 0; o >>= 1)
        hsum += __shfl_down_sync(0xffffffffu, hsum, o);
    if ((tid & 31) == 0) RED[tid >> 5] = hsum;
    __syncthreads();
    if (tid < 32) {
        float v = (tid < 16) ? RED[tid] : 0.f;
#pragma unroll
        for (int o = 8; o > 0; o >>= 1)
            v += __shfl_down_sync(0xffffffffu, v, o);
        if (tid == 0) {
            int tile_id = zhalf * 9 + blockIdx.y * 3 + blockIdx.x;
            g_part[c * NTILE + tile_id] = v;
        }
    }
#undef SUB2
#undef DO_ST1
#undef DO_ST2
}

__global__ void topk_kernel() {
    if (threadIdx.x == 0 && blockIdx.x == 0) {
        double v[NCH];
        bool used[NCH];
        for (int i = 0; i < NCH; i++) {
            double s = 0.0;
            for (int t = 0; t < NTILE; t++) s += (double)g_part[i * NTILE + t];
            v[i] = s; used[i] = false;
        }
        for (int k = 0; k < KOUT; k++) {
            int bi = 0; double bv = -1e300; bool found = false;
            for (int i = 0; i < NCH; i++) {
                if (!used[i] && (!found || v[i] > bv)) { bv = v[i]; bi = i; found = true; }
            }
            used[bi] = true;
            g_idx[k] = bi;
        }
    }
}

// Gather: 256 threads x 4 float4; 1024 float4 per block; 1152 blocks.
__global__ __launch_bounds__(256) void gather_kernel(const float* __restrict__ x,
                                                     float* __restrict__ out) {
    const int per_ch_v = CH_STRIDE / 4;          // 147456
    const int chunks_per_ch = per_ch_v / 1024;   // 144
    int k = blockIdx.x / chunks_per_ch;
    int chunk = blockIdx.x - k * chunks_per_ch;
    int c = g_idx[k];
    const float4* src = reinterpret_cast<const float4*>(x + (size_t)c * CH_STRIDE);
    float4* dst = reinterpret_cast<float4*>(out) + (size_t)k * per_ch_v;
    int base = chunk * 1024 + threadIdx.x;
    float4 v0 = src[base];
    float4 v1 = src[base + 256];
    float4 v2 = src[base + 512];
    float4 v3 = src[base + 768];
    dst[base]       = v0;
    dst[base + 256] = v1;
    dst[base + 512] = v2;
    dst[base + 768] = v3;
}

extern "C" void kernel_launch(void* const* d_in, const int* in_sizes, int n_in,
                              void* d_out, int out_size) {
    const float* x = (const float*)d_in[0];
    float* out = (float*)d_out;

    dim3 grid(3, 3, NCH * 2);
    harris_kernel<<<grid, 512>>>(x);
    topk_kernel<<<1, 1>>>();
    const int gather_blocks = KOUT * ((CH_STRIDE / 4) / 1024);  // 1152
    gather_kernel<<<gather_blocks, 256>>>(x, out);
}